// round 16
// baseline (speedup 1.0000x reference)
#include <cuda_runtime.h>
#include <cuda_fp16.h>
#include <cstdint>

#define B_ 2
#define N_ 2048
#define D_ 2048
#define H_ 16
#define HD_ 128
#define CH_ 128
#define NC_ (N_/CH_)          // 16
#define QKVS_ (3*H_*HD_)      // 6144
#define NCOMB (QKVS_ + D_)    // 8192

// -------- fp16 tensor-core GEMM config: BM128 x BN64, 3 CTAs/SM --------
#define BM 128
#define BN 64
#define BK 64
#define STAGES 3
#define STAGE_A (BM * BK * 2)                // 16384
#define STAGE_B (BN * BK * 2)                // 8192
#define STAGE_BYTES (STAGE_A + STAGE_B)      // 24576
#define SM_TC_TOTAL (1024 + STAGES * STAGE_BYTES)   // 74752 -> 3 CTAs/SM

// ---------------- scratch ----------------
__device__ __half g_qkvh[(size_t)B_ * N_ * QKVS_];
__device__ __half g_gateh[(size_t)B_ * N_ * D_];
__device__ float g_O[(size_t)B_ * N_ * D_];
__device__ float g_A[(size_t)B_ * H_ * NC_ * HD_ * HD_];   // [d][e]
__device__ __half g_KVh[(size_t)B_ * H_ * NC_ * HD_ * HD_];
__device__ __half g_xh[(size_t)B_ * N_ * D_];
__device__ __half g_yh[(size_t)B_ * N_ * D_];
__device__ __half g_wch[(size_t)NCOMB * D_];
__device__ __half g_woh[(size_t)D_ * H_ * HD_];

// ---------------- helpers ----------------
__device__ __forceinline__ uint32_t smem_u32(const void* p) {
    uint32_t a;
    asm("{ .reg .u64 t; cvta.to.shared.u64 t, %1; cvt.u32.u64 %0, t; }" : "=r"(a) : "l"(p));
    return a;
}
__device__ __forceinline__ void cp_async16(uint32_t dst, const void* src) {
    asm volatile("cp.async.cg.shared.global [%0], [%1], 16;" :: "r"(dst), "l"(src));
}
__device__ __forceinline__ void ldsm_x4(uint32_t* r, uint32_t addr) {
    asm volatile("ldmatrix.sync.aligned.m8n8.x4.shared.b16 {%0,%1,%2,%3}, [%4];"
                 : "=r"(r[0]), "=r"(r[1]), "=r"(r[2]), "=r"(r[3]) : "r"(addr));
}
__device__ __forceinline__ void ldsm_x4_t(uint32_t* r, uint32_t addr) {
    asm volatile("ldmatrix.sync.aligned.m8n8.x4.trans.shared.b16 {%0,%1,%2,%3}, [%4];"
                 : "=r"(r[0]), "=r"(r[1]), "=r"(r[2]), "=r"(r[3]) : "r"(addr));
}
__device__ __forceinline__ void mma16n8k16h(float* c, const uint32_t* a, const uint32_t* b) {
    asm volatile("mma.sync.aligned.m16n8k16.row.col.f32.f16.f16.f32 "
                 "{%0,%1,%2,%3}, {%4,%5,%6,%7}, {%8,%9}, {%0,%1,%2,%3};"
                 : "+f"(c[0]), "+f"(c[1]), "+f"(c[2]), "+f"(c[3])
                 : "r"(a[0]), "r"(a[1]), "r"(a[2]), "r"(a[3]), "r"(b[0]), "r"(b[1]));
}
__device__ __forceinline__ float act_apply(float v, int act) {
    if (act == 1) return v / (1.f + __expf(-v));
    if (act == 2) return 1.f / (1.f + __expf(-v));
    return v;
}

// ---------------- fused fp32 -> fp16 conversions ----------------
__device__ __forceinline__ void f2h_range(const float4* __restrict__ in,
                                          uint2* __restrict__ out, int n4,
                                          int gid, int gstride)
{
    for (int i = gid; i < n4; i += gstride) {
        float4 v = in[i];
        __half2 h0 = __float22half2_rn(make_float2(v.x, v.y));
        __half2 h1 = __float22half2_rn(make_float2(v.z, v.w));
        uint2 o;
        o.x = *(uint32_t*)&h0;
        o.y = *(uint32_t*)&h1;
        out[i] = o;
    }
}
__global__ __launch_bounds__(256) void f2h4_k(
    const float4* i0, uint2* o0, int n0,
    const float4* i1, uint2* o1, int n1,
    const float4* i2, uint2* o2, int n2,
    const float4* i3, uint2* o3, int n3)
{
    int gid = blockIdx.x * 256 + threadIdx.x;
    int gstride = gridDim.x * 256;
    f2h_range(i0, o0, n0, gid, gstride);
    f2h_range(i1, o1, n1, gid, gstride);
    f2h_range(i2, o2, n2, gid, gstride);
    f2h_range(i3, o3, n3, gid, gstride);
}

// ======= GEMM mainloop: 256 threads, warp grid 2(m) x 4(n), warp tile 64x16 =======
#define GEMM_MAINLOOP(A_, Bm_, K_)                                                   \
    const int NK = (K_) / BK;                                                        \
    const int row8 = tid >> 3, seg = tid & 7;                                        \
    const int lane = tid & 31, w = tid >> 5;                                         \
    const int wm = (w >> 2) * 64;                                                    \
    const int wn = (w & 3) * 16;                                                     \
    const int tr = lane >> 2, tc = lane & 3;                                         \
    const uint32_t mrowA = (uint32_t)(wm + (lane & 15));                             \
    const uint32_t swzA  = (mrowA & 7) << 4;                                         \
    const uint32_t la16  = (uint32_t)(lane & 16);                                    \
    const uint32_t aRow  = mrowA * 128;                                              \
    const uint32_t nrowB = (uint32_t)(wn + (lane & 7) + ((lane & 16) >> 1));         \
    const uint32_t swzB  = (nrowB & 7) << 4;                                         \
    const uint32_t lb16  = (uint32_t)((lane & 8) << 1);                              \
    const uint32_t bRow  = nrowB * 128;                                              \
    float acc[4][2][4];                                                              \
    _Pragma("unroll")                                                                \
    for (int i = 0; i < 4; i++)                                                      \
        _Pragma("unroll")                                                            \
        for (int j = 0; j < 2; j++)                                                  \
            _Pragma("unroll")                                                        \
            for (int q = 0; q < 4; q++) acc[i][j][q] = 0.f;                          \
    auto load_stage = [&](int s, int kidx) {                                         \
        uint32_t a_s = sbase + 1024 + s * STAGE_BYTES;                               \
        uint32_t b_s = a_s + STAGE_A;                                                \
        const __half* ag = (A_) + (size_t)bm * (K_) + kidx * BK + seg * 8;           \
        const __half* bg = (Bm_) + (size_t)bn * (K_) + kidx * BK + seg * 8;          \
        _Pragma("unroll")                                                            \
        for (int i = 0; i < 4; i++) {                                                \
            int r = row8 + i * 32;                                                   \
            uint32_t off = r * 128 + seg * 16;                                       \
            uint32_t sw = off ^ ((off >> 3) & 0x70);                                 \
            cp_async16(a_s + sw, ag + (size_t)r * (K_));                             \
        }                                                                            \
        _Pragma("unroll")                                                            \
        for (int i = 0; i < 2; i++) {                                                \
            int r = row8 + i * 32;                                                   \
            uint32_t off = r * 128 + seg * 16;                                       \
            uint32_t sw = off ^ ((off >> 3) & 0x70);                                 \
            cp_async16(b_s + sw, bg + (size_t)r * (K_));                             \
        }                                                                            \
        asm volatile("cp.async.commit_group;" ::: "memory");                         \
    };                                                                               \
    load_stage(0, 0); load_stage(1, 1);                                              \
    int buf = 0, lbuf = 2;                                                           \
    for (int ks = 0; ks < NK; ks++) {                                                \
        if (ks + 1 < NK) asm volatile("cp.async.wait_group 1;" ::: "memory");        \
        else             asm volatile("cp.async.wait_group 0;" ::: "memory");        \
        __syncthreads();                                                             \
        if (ks + 2 < NK) {                                                           \
            load_stage(lbuf, ks + 2);                                                \
            lbuf = (lbuf == STAGES - 1) ? 0 : lbuf + 1;                              \
        }                                                                            \
        const uint32_t a_s = sbase + 1024 + buf * STAGE_BYTES;                       \
        const uint32_t b_s = a_s + STAGE_A;                                          \
        buf = (buf == STAGES - 1) ? 0 : buf + 1;                                     \
        _Pragma("unroll")                                                            \
        for (int ksl = 0; ksl < 4; ksl++) {                                          \
            const uint32_t cbA = (((uint32_t)(ksl * 32)) | la16) ^ swzA;             \
            const uint32_t cbB = (((uint32_t)(ksl * 32)) | lb16) ^ swzB;             \
            uint32_t av[4][4], bq[4];                                                \
            _Pragma("unroll")                                                        \
            for (int i = 0; i < 4; i++)                                              \
                ldsm_x4(av[i], a_s + aRow + i * 2048 + cbA);                         \
            ldsm_x4(bq, b_s + bRow + cbB);                                           \
            _Pragma("unroll")                                                        \
            for (int i = 0; i < 4; i++) {                                            \
                mma16n8k16h(acc[i][0], av[i], bq);                                   \
                mma16n8k16h(acc[i][1], av[i], bq + 2);                               \
            }                                                                        \
        }                                                                            \
    }

// ---------------- merged projection GEMM: [silu(x Wqkv^T) | sigmoid(x Wg^T)] ----------------
__global__ __launch_bounds__(256, 3) void gemm_proj(
    const __half* __restrict__ A, const __half* __restrict__ Bm)
{
    extern __shared__ char smem[];
    const uint32_t sbase = smem_u32(smem);
    const int tid = threadIdx.x;
    const int bm = blockIdx.y * BM, bn = blockIdx.x * BN;

    GEMM_MAINLOOP(A, Bm, D_)

    if (bn < QKVS_) {
        __half* C = g_qkvh;
#pragma unroll
        for (int i = 0; i < 4; i++) {
#pragma unroll
            for (int j = 0; j < 2; j++) {
                int r0 = bm + wm + i * 16 + tr;
                int c0 = bn + wn + j * 8 + 2 * tc;
                __half2 v0 = __float22half2_rn(make_float2(act_apply(acc[i][j][0], 1),
                                                           act_apply(acc[i][j][1], 1)));
                __half2 v1 = __float22half2_rn(make_float2(act_apply(acc[i][j][2], 1),
                                                           act_apply(acc[i][j][3], 1)));
                *(__half2*)(C + (size_t)r0 * QKVS_ + c0) = v0;
                *(__half2*)(C + (size_t)(r0 + 8) * QKVS_ + c0) = v1;
            }
        }
    } else {
        __half* C = g_gateh;
        int cbase = bn - QKVS_;
#pragma unroll
        for (int i = 0; i < 4; i++) {
#pragma unroll
            for (int j = 0; j < 2; j++) {
                int r0 = bm + wm + i * 16 + tr;
                int c0 = cbase + wn + j * 8 + 2 * tc;
                __half2 v0 = __float22half2_rn(make_float2(act_apply(acc[i][j][0], 2),
                                                           act_apply(acc[i][j][1], 2)));
                __half2 v1 = __float22half2_rn(make_float2(act_apply(acc[i][j][2], 2),
                                                           act_apply(acc[i][j][3], 2)));
                *(__half2*)(C + (size_t)r0 * D_ + c0) = v0;
                *(__half2*)(C + (size_t)(r0 + 8) * D_ + c0) = v1;
            }
        }
    }
}

// ---------------- final projection GEMM: out = y @ Wo^T (fp32 out) ----------------
__global__ __launch_bounds__(256, 3) void gemm_out(
    const __half* __restrict__ A, const __half* __restrict__ Bm,
    float* __restrict__ C)
{
    extern __shared__ char smem[];
    const uint32_t sbase = smem_u32(smem);
    const int tid = threadIdx.x;
    const int bm = blockIdx.y * BM, bn = blockIdx.x * BN;

    GEMM_MAINLOOP(A, Bm, D_)

#pragma unroll
    for (int i = 0; i < 4; i++) {
#pragma unroll
        for (int j = 0; j < 2; j++) {
            int r0 = bm + wm + i * 16 + tr;
            int c0 = bn + wn + j * 8 + 2 * tc;
            float2 v0, v1;
            v0.x = acc[i][j][0];
            v0.y = acc[i][j][1];
            v1.x = acc[i][j][2];
            v1.y = acc[i][j][3];
            *(float2*)(C + (size_t)r0 * D_ + c0) = v0;
            *(float2*)(C + (size_t)(r0 + 8) * D_ + c0) = v1;
        }
    }
}

// ---------------- phase 1: fp16 tensor-core intra attention + KV summary ----------------
#define ROWB 256
#define P1_SMEM (3*128*ROWB + 3*128*4)
__global__ __launch_bounds__(256, 2) void attn_phase1(const float* __restrict__ slope)
{
    extern __shared__ char smc[];
    const uint32_t sb = smem_u32(smc);
    const uint32_t bQ = sb;                    // Q -> S
    const uint32_t bK = sb + 128*ROWB;         // K natural
    const uint32_t bV = sb + 2*128*ROWB;       // V natural
    float* ei = (float*)(smc + 3*128*ROWB);
    float* ej = ei + 128;
    __half* wdh = (__half*)(ej + 128);

    const int c = blockIdx.x, h = blockIdx.y, b = blockIdx.z;
    const int tid = threadIdx.x, lane = tid & 31, w = tid >> 5;
    const int tr = lane >> 2, tc = lane & 3;
    const int wm = (w >> 2) * 64, wn = (w & 3) * 32;
    const float sl = slope[h];
    if (tid < 128) {
        ei[tid] = __expf(-sl * (float)tid);
        ej[tid] = __expf( sl * (float)tid);
        wdh[tid] = __float2half(__expf(-sl * (float)(127 - tid)));
    }

    const __half* base = g_qkvh + ((size_t)(b*N_ + c*CH_)) * QKVS_ + h * (3*HD_);

#pragma unroll
    for (int it = 0; it < 8; it++) {
        int idx = tid + it * 256;
        int row = idx >> 4, sg = idx & 15;
        uint32_t cb = (uint32_t)(sg * 16) ^ (uint32_t)((row & 7) << 4);
        const __half* rp = base + (size_t)row * QKVS_;
        *(uint4*)(smc + (bQ - sb) + row*ROWB + cb) = *(const uint4*)(rp + sg*8);
        *(uint4*)(smc + (bK - sb) + row*ROWB + cb) = *(const uint4*)(rp + HD_ + sg*8);
        *(uint4*)(smc + (bV - sb) + row*ROWB + cb) = *(const uint4*)(rp + 2*HD_ + sg*8);
    }
    __syncthreads();

    const uint32_t swz  = (uint32_t)((lane & 7) << 4);
    const uint32_t la16 = (uint32_t)(lane & 16);
    const uint32_t lb16 = (uint32_t)((lane & 8) << 1);
    const uint32_t aOff = (uint32_t)((wm + (lane & 15)) * ROWB);
    const uint32_t bOff = (uint32_t)((wn + (lane & 7) + ((lane & 16) >> 1)) * ROWB);
    const uint32_t aTrow = (uint32_t)(((lane & 7) + ((lane & 16) >> 1)) * ROWB);
    const uint32_t bTrow = (uint32_t)(((lane & 7) + (lane & 8)) * ROWB);
    uint32_t aTcol[4];
#pragma unroll
    for (int i = 0; i < 4; i++)
        aTcol[i] = (uint32_t)((wm + i*16 + (lane & 8)) * 2) ^ swz;
    uint32_t bTcol[2];
#pragma unroll
    for (int p = 0; p < 2; p++)
        bTcol[p] = (uint32_t)((wn + p*16 + ((lane & 16) >> 1)) * 2) ^ swz;

    float acc[4][4][4];
    // ---- mma1: S = Q K^T ----
#pragma unroll
    for (int i = 0; i < 4; i++)
#pragma unroll
        for (int j = 0; j < 4; j++)
#pragma unroll
            for (int q = 0; q < 4; q++) acc[i][j][q] = 0.f;
#pragma unroll
    for (int kc = 0; kc < 8; kc++) {
        uint32_t cbA = (((uint32_t)(kc * 32)) | la16) ^ swz;
        uint32_t cbB = (((uint32_t)(kc * 32)) | lb16) ^ swz;
        uint32_t av[4][4], bq[2][4];
#pragma unroll
        for (int i = 0; i < 4; i++) ldsm_x4(av[i], bQ + aOff + i*4096 + cbA);
#pragma unroll
        for (int p = 0; p < 2; p++) ldsm_x4(bq[p], bK + bOff + p*4096 + cbB);
#pragma unroll
        for (int i = 0; i < 4; i++)
#pragma unroll
            for (int j = 0; j < 4; j++)
                mma16n8k16h(acc[i][j], av[i], (j & 1) ? bq[j >> 1] + 2 : bq[j >> 1]);
    }
    __syncthreads();

    // ---- decay mask, store S (fp16) into bQ ----
#pragma unroll
    for (int i = 0; i < 4; i++) {
        int i0 = wm + i*16 + tr;
        float ei0 = ei[i0], ei1 = ei[i0 + 8];
        uint32_t sz = (uint32_t)((i0 & 7) << 4);
#pragma unroll
        for (int j = 0; j < 4; j++) {
            int j0 = wn + j*8 + 2*tc;
            float ej0 = ej[j0], ej1 = ej[j0 + 1];
            float s00 = (j0     <= i0    ) ? acc[i][j][0] * (ei0*ej0) : 0.f;
            float s01 = (j0 + 1 <= i0    ) ? acc[i][j][1] * (ei0*ej1) : 0.f;
            float s10 = (j0     <= i0 + 8) ? acc[i][j][2] * (ei1*ej0) : 0.f;
            float s11 = (j0 + 1 <= i0 + 8) ? acc[i][j][3] * (ei1*ej1) : 0.f;
            uint32_t dc = ((uint32_t)(j0 * 2)) ^ sz;
            *(__half2*)(smc + (bQ - sb) + i0*ROWB + dc) =
                __float22half2_rn(make_float2(s00, s01));
            *(__half2*)(smc + (bQ - sb) + (i0+8)*ROWB + dc) =
                __float22half2_rn(make_float2(s10, s11));
        }
    }
    __syncthreads();

    // ---- mma2 (O = S V) + mma3 (A = V^T (K*w)) fused loop ----
    float acco[4][4][4];
#pragma unroll
    for (int i = 0; i < 4; i++)
#pragma unroll
        for (int j = 0; j < 4; j++)
#pragma unroll
            for (int q = 0; q < 4; q++) { acc[i][j][q] = 0.f; acco[i][j][q] = 0.f; }

    const int kt = 2 * (lane & 3);

#pragma unroll
    for (int kc = 0; kc < 8; kc++) {
        uint32_t cbA = (((uint32_t)(kc * 32)) | la16) ^ swz;
        uint32_t kRow = (uint32_t)(kc * 16) * ROWB;
        uint32_t av[4][4], bq[2][4];
#pragma unroll
        for (int i = 0; i < 4; i++) ldsm_x4(av[i], bQ + aOff + i*4096 + cbA);
#pragma unroll
        for (int p = 0; p < 2; p++) ldsm_x4_t(bq[p], bV + bTrow + kRow + bTcol[p]);
#pragma unroll
        for (int i = 0; i < 4; i++)
#pragma unroll
            for (int j = 0; j < 4; j++)
                mma16n8k16h(acco[i][j], av[i], (j & 1) ? bq[j >> 1] + 2 : bq[j >> 1]);
        uint32_t wlo = *(const uint32_t*)(wdh + kc*16 + kt);
        uint32_t whi = *(const uint32_t*)(wdh + kc*16 + kt + 8);
        uint32_t avv[4][4], bk[2][4];
#pragma unroll
        for (int i = 0; i < 4; i++) ldsm_x4_t(avv[i], bV + aTrow + kRow + aTcol[i]);
#pragma unroll
        for (int p = 0; p < 2; p++) {
            ldsm_x4_t(bk[p], bK + bTrow + kRow + bTcol[p]);
            __half2 w0 = *(__half2*)&wlo, w1 = *(__half2*)&whi;
            __half2* bh = (__half2*)bk[p];
            bh[0] = __hmul2(bh[0], w0);
            bh[1] = __hmul2(bh[1], w1);
            bh[2] = __hmul2(bh[2], w0);
            bh[3] = __hmul2(bh[3], w1);
        }
#pragma unroll
        for (int i = 0; i < 4; i++)
#pragma unroll
            for (int j = 0; j < 4; j++)
                mma16n8k16h(acc[i][j], avv[i], (j & 1) ? bk[j >> 1] + 2 : bk[j >> 1]);
    }
    {
        float* obase = g_O + ((size_t)(b*N_ + c*CH_)) * D_ + h*HD_;
        float* abase = g_A + (((size_t)(b*H_ + h))*NC_ + c) * (HD_*HD_);
#pragma unroll
        for (int i = 0; i < 4; i++) {
            int i0 = wm + i*16 + tr;
#pragma unroll
            for (int j = 0; j < 4; j++) {
                int j0 = wn + j*8 + 2*tc;
                float2 v0 = { acco[i][j][0], acco[i][j][1] };
                float2 v1 = { acco[i][j][2], acco[i][j][3] };
                *(float2*)(obase + (size_t)i0 * D_ + j0) = v0;
                *(float2*)(obase + (size_t)(i0+8) * D_ + j0) = v1;
                float2 a0 = { acc[i][j][0], acc[i][j][1] };
                float2 a1 = { acc[i][j][2], acc[i][j][3] };
                *(float2*)(abase + i0*HD_ + j0) = a0;
                *(float2*)(abase + (i0+8)*HD_ + j0) = a1;
            }
        }
    }
}

// ---------------- phase 2: chunk-state scan, prefetch + fp16 KV output ----------------
__global__ __launch_bounds__(256) void attn_phase2(
    const float* __restrict__ past_kv, const float* __restrict__ slope,
    float* __restrict__ kv_out, int write_kv)
{
    const int bh = blockIdx.x;
    const int h = bh & (H_ - 1);
    const int tid = threadIdx.x;
    const float lamC = __expf(-slope[h] * (float)CH_);
    const size_t eb = (size_t)blockIdx.y * 1024 + tid;
    const size_t pb = (size_t)bh * (HD_*HD_);
    float st[4], cur[4], nxt[4];
#pragma unroll
    for (int t = 0; t < 4; t++) {
        size_t i = eb + (size_t)t*256;
        st[t] = past_kv[pb + (i & 127)*HD_ + (i >> 7)];
    }
    {
        const size_t kb0 = ((size_t)bh*NC_) * (HD_*HD_);
#pragma unroll
        for (int t = 0; t < 4; t++) cur[t] = g_A[kb0 + eb + t*256];
    }
    for (int c = 0; c < NC_; c++) {
        const size_t kb = ((size_t)bh*NC_ + c) * (HD_*HD_);
        if (c + 1 < NC_) {
            const size_t kbn = kb + (HD_*HD_);
#pragma unroll
            for (int t = 0; t < 4; t++) nxt[t] = g_A[kbn + eb + t*256];
        }
#pragma unroll
        for (int t = 0; t < 4; t++) {
            g_KVh[kb + eb + t*256] = __float2half(st[t]);
            st[t] = fmaf(lamC, st[t], cur[t]);
            cur[t] = nxt[t];
        }
    }
    if (write_kv) {
#pragma unroll
        for (int t = 0; t < 4; t++) {
            size_t i = eb + (size_t)t*256;
            kv_out[pb + (i & 127)*HD_ + (i >> 7)] = st[t];
        }
    }
}

// ---------------- phase 3: O += lambda^(i+1) * Q KV0 (fp16 tensor cores) ----------------
#define P3_SMEM (2*128*ROWB + 128*4)
__global__ __launch_bounds__(256, 2) void attn_phase3(const float* __restrict__ slope)
{
    extern __shared__ char smc[];
    const uint32_t sb = smem_u32(smc);
    const uint32_t bQ  = sb;
    const uint32_t bKV = sb + 128*ROWB;
    float* e2 = (float*)(smc + 2*128*ROWB);

    const int c = blockIdx.x, h = blockIdx.y, b = blockIdx.z;
    const int tid = threadIdx.x, lane = tid & 31, w = tid >> 5;
    const int tr = lane >> 2, tc = lane & 3;
    const int wm = (w >> 2) * 64, wn = (w & 3) * 32;
    const float sl = slope[h];
    if (tid < 128) e2[tid] = __expf(-sl * (float)(tid + 1));

    const __half* qbase  = g_qkvh + ((size_t)(b*N_ + c*CH_)) * QKVS_ + h * (3*HD_);
    const __half* kvbase = g_KVh + (((size_t)(b*H_ + h))*NC_ + c) * (HD_*HD_);
#pragma unroll
    for (int it = 0; it < 8; it++) {
        int idx = tid + it * 256;
        int row = idx >> 4, sg = idx & 15;
        uint32_t cb = (uint32_t)(sg * 16) ^ (uint32_t)((row & 7) << 4);
        *(uint4*)(smc + (bQ - sb) + row*ROWB + cb) =
            *(const uint4*)(qbase + (size_t)row * QKVS_ + sg*8);
        *(uint4*)(smc + (bKV - sb) + row*ROWB + cb) =
            *(const uint4*)(kvbase + (size_t)row * HD_ + sg*8);
    }
    __syncthreads();

    const uint32_t swz   = (uint32_t)((lane & 7) << 4);
    const uint32_t la16  = (uint32_t)(lane & 16);
    const uint32_t lb16  = (uint32_t)((lane & 8) << 1);
    const uint32_t aOff  = (uint32_t)((wm + (lane & 15)) * ROWB);
    const uint32_t bOff  = (uint32_t)((wn + (lane & 7) + ((lane & 16) >> 1)) * ROWB);

    float acc[4][4][4];
#pragma unroll
    for (int i = 0; i < 4; i++)
#pragma unroll
        for (int j = 0; j < 4; j++)
#pragma unroll
            for (int q = 0; q < 4; q++) acc[i][j][q] = 0.f;

#pragma unroll
    for (int kc = 0; kc < 8; kc++) {
        uint32_t cbA = (((uint32_t)(kc * 32)) | la16) ^ swz;
        uint32_t cbB = (((uint32_t)(kc * 32)) | lb16) ^ swz;
        uint32_t av[4][4], bq[2][4];
#pragma unroll
        for (int i = 0; i < 4; i++) ldsm_x4(av[i], bQ + aOff + i*4096 + cbA);
#pragma unroll
        for (int p = 0; p < 2; p++) ldsm_x4(bq[p], bKV + bOff + p*4096 + cbB);
#pragma unroll
        for (int i = 0; i < 4; i++)
#pragma unroll
            for (int j = 0; j < 4; j++)
                mma16n8k16h(acc[i][j], av[i], (j & 1) ? bq[j >> 1] + 2 : bq[j >> 1]);
    }

    float* obase = g_O + ((size_t)(b*N_ + c*CH_)) * D_ + h*HD_;
#pragma unroll
    for (int i = 0; i < 4; i++) {
        int i0 = wm + i*16 + tr;
        float s0 = e2[i0], s1 = e2[i0 + 8];
#pragma unroll
        for (int j = 0; j < 4; j++) {
            int j0 = wn + j*8 + 2*tc;
            float2* p0 = (float2*)(obase + (size_t)i0 * D_ + j0);
            float2* p1 = (float2*)(obase + (size_t)(i0+8) * D_ + j0);
            float2 v0 = *p0, v1 = *p1;
            v0.x = fmaf(s0, acc[i][j][0], v0.x);
            v0.y = fmaf(s0, acc[i][j][1], v0.y);
            v1.x = fmaf(s1, acc[i][j][2], v1.x);
            v1.y = fmaf(s1, acc[i][j][3], v1.y);
            *p0 = v0; *p1 = v1;
        }
    }
}

// ---------------- RMSNorm * gate(fp16) -> y (fp16) ----------------
__global__ __launch_bounds__(256) void rmsnorm_gate_k(const float* __restrict__ norm_w)
{
    const int row = blockIdx.x;
    const int tid = threadIdx.x;
    const float4* o4 = (const float4*)(g_O + (size_t)row * D_);
    const __half2* gh = (const __half2*)(g_gateh + (size_t)row * D_);
    const float4* w4 = (const float4*)norm_w;
    __half2* yh = (__half2*)(g_yh + (size_t)row * D_);

    float4 v0 = o4[tid], v1 = o4[tid + 256];
    float s = v0.x*v0.x + v0.y*v0.y + v0.z*v0.z + v0.w*v0.w
            + v1.x*v1.x + v1.y*v1.y + v1.z*v1.z + v1.w*v1.w;
#pragma unroll
    for (int off = 16; off; off >>= 1) s += __shfl_xor_sync(0xffffffffu, s, off);
    __shared__ float red[8];
    if ((tid & 31) == 0) red[tid >> 5] = s;
    __syncthreads();
    float tot = red[0] + red[1] + red[2] + red[3] + red[4] + red[5] + red[6] + red[7];
    float r = rsqrtf(tot * (1.f / (float)D_) + 1e-6f);

    float2 g0 = __half22float2(gh[2*tid]);
    float2 g1 = __half22float2(gh[2*tid + 1]);
    float2 g2 = __half22float2(gh[2*(tid + 256)]);
    float2 g3 = __half22float2(gh[2*(tid + 256) + 1]);
    float4 w0 = w4[tid], w1 = w4[tid + 256];
    yh[2*tid]         = __float22half2_rn(make_float2(g0.x*w0.x*v0.x*r, g0.y*w0.y*v0.y*r));
    yh[2*tid+1]       = __float22half2_rn(make_float2(g1.x*w0.z*v0.z*r, g1.y*w0.w*v0.w*r));
    yh[2*(tid+256)]   = __float22half2_rn(make_float2(g2.x*w1.x*v1.x*r, g2.y*w1.y*v1.y*r));
    yh[2*(tid+256)+1] = __float22half2_rn(make_float2(g3.x*w1.z*v1.z*r, g3.y*w1.w*v1.w*r));
}

// ---------------- launch ----------------
extern "C" void kernel_launch(void* const* d_in, const int* in_sizes, int n_in,
                              void* d_out, int out_size)
{
    const float* x       = (const float*)d_in[0];
    const float* past_kv = (const float*)d_in[1];
    const float* slope   = (const float*)d_in[2];
    const float* w_qkv   = (const float*)d_in[3];
    const float* w_gate  = (const float*)d_in[4];
    const float* w_out   = (const float*)d_in[5];
    const float* norm_w  = (const float*)d_in[6];
    float* out = (float*)d_out;

    __half *xh_p, *yh_p, *wch_p, *woh_p;
    cudaGetSymbolAddress((void**)&xh_p, g_xh);
    cudaGetSymbolAddress((void**)&yh_p, g_yh);
    cudaGetSymbolAddress((void**)&wch_p, g_wch);
    cudaGetSymbolAddress((void**)&woh_p, g_woh);

    cudaFuncSetAttribute(attn_phase1, cudaFuncAttributeMaxDynamicSharedMemorySize, P1_SMEM);
    cudaFuncSetAttribute(attn_phase3, cudaFuncAttributeMaxDynamicSharedMemorySize, P3_SMEM);
    cudaFuncSetAttribute(gemm_proj, cudaFuncAttributeMaxDynamicSharedMemorySize, SM_TC_TOTAL);
    cudaFuncSetAttribute(gemm_out, cudaFuncAttributeMaxDynamicSharedMemorySize, SM_TC_TOTAL);

    const int M = B_ * N_;   // 4096

    f2h4_k<<<2048, 256>>>((const float4*)x, (uint2*)xh_p, (B_*N_*D_)/4,
                          (const float4*)w_qkv, (uint2*)wch_p, (QKVS_*D_)/4,
                          (const float4*)w_gate, (uint2*)(wch_p + (size_t)QKVS_*D_), (H_*HD_*D_)/4,
                          (const float4*)w_out, (uint2*)woh_p, (D_*H_*HD_)/4);

    gemm_proj<<<dim3(NCOMB/BN, M/BM), 256, SM_TC_TOTAL>>>(xh_p, wch_p);
    attn_phase1<<<dim3(NC_, H_, B_), 256, P1_SMEM>>>(slope);
    int write_kv = (out_size >= (int)(B_*N_*D_ + B_*H_*HD_*HD_)) ? 1 : 0;
    attn_phase2<<<dim3(B_*H_, 16), 256>>>(past_kv, slope, out + (size_t)B_*N_*D_, write_kv);
    attn_phase3<<<dim3(NC_, H_, B_), 256, P3_SMEM>>>(slope);
    rmsnorm_gate_k<<<M, 256>>>(norm_w);
    gemm_out<<<dim3(D_/BN, M/BM), 256, SM_TC_TOTAL>>>(yh_p, woh_p, out);
}

// round 17
// speedup vs baseline: 1.1305x; 1.1305x over previous
#include <cuda_runtime.h>
#include <cuda_fp16.h>
#include <cstdint>

#define B_ 2
#define N_ 2048
#define D_ 2048
#define H_ 16
#define HD_ 128
#define CH_ 128
#define NC_ (N_/CH_)          // 16
#define QKVS_ (3*H_*HD_)      // 6144
#define NCOMB (QKVS_ + D_)    // 8192

// -------- fp16 tensor-core GEMM config (proven optimum: 2 CTAs/SM) --------
#define BM 128
#define BN 128
#define BK 64
#define STAGES 3
#define STAGE_BYTES ((BM + BN) * BK * 2)     // 32768
#define SM_TC_TOTAL (1024 + STAGES * STAGE_BYTES)

// ---------------- scratch ----------------
__device__ __half g_qkvh[(size_t)B_ * N_ * QKVS_];
__device__ __half g_gateh[(size_t)B_ * N_ * D_];
__device__ float g_O[(size_t)B_ * N_ * D_];
__device__ float g_A[(size_t)B_ * H_ * NC_ * HD_ * HD_];   // [d][e]
__device__ __half g_KVh[(size_t)B_ * H_ * NC_ * HD_ * HD_];
__device__ __half g_xh[(size_t)B_ * N_ * D_];
__device__ __half g_yh[(size_t)B_ * N_ * D_];
__device__ __half g_wch[(size_t)NCOMB * D_];
__device__ __half g_woh[(size_t)D_ * H_ * HD_];

// ---------------- helpers ----------------
__device__ __forceinline__ uint32_t smem_u32(const void* p) {
    uint32_t a;
    asm("{ .reg .u64 t; cvta.to.shared.u64 t, %1; cvt.u32.u64 %0, t; }" : "=r"(a) : "l"(p));
    return a;
}
__device__ __forceinline__ void cp_async16(uint32_t dst, const void* src) {
    asm volatile("cp.async.cg.shared.global [%0], [%1], 16;" :: "r"(dst), "l"(src));
}
__device__ __forceinline__ void ldsm_x4(uint32_t* r, uint32_t addr) {
    asm volatile("ldmatrix.sync.aligned.m8n8.x4.shared.b16 {%0,%1,%2,%3}, [%4];"
                 : "=r"(r[0]), "=r"(r[1]), "=r"(r[2]), "=r"(r[3]) : "r"(addr));
}
__device__ __forceinline__ void ldsm_x4_t(uint32_t* r, uint32_t addr) {
    asm volatile("ldmatrix.sync.aligned.m8n8.x4.trans.shared.b16 {%0,%1,%2,%3}, [%4];"
                 : "=r"(r[0]), "=r"(r[1]), "=r"(r[2]), "=r"(r[3]) : "r"(addr));
}
__device__ __forceinline__ void mma16n8k16h(float* c, const uint32_t* a, const uint32_t* b) {
    asm volatile("mma.sync.aligned.m16n8k16.row.col.f32.f16.f16.f32 "
                 "{%0,%1,%2,%3}, {%4,%5,%6,%7}, {%8,%9}, {%0,%1,%2,%3};"
                 : "+f"(c[0]), "+f"(c[1]), "+f"(c[2]), "+f"(c[3])
                 : "r"(a[0]), "r"(a[1]), "r"(a[2]), "r"(a[3]), "r"(b[0]), "r"(b[1]));
}
__device__ __forceinline__ float act_apply(float v, int act) {
    if (act == 1) return v / (1.f + __expf(-v));
    if (act == 2) return 1.f / (1.f + __expf(-v));
    return v;
}

// ---------------- fused fp32 -> fp16 conversions ----------------
__device__ __forceinline__ void f2h_range(const float4* __restrict__ in,
                                          uint2* __restrict__ out, int n4,
                                          int gid, int gstride)
{
    for (int i = gid; i < n4; i += gstride) {
        float4 v = in[i];
        __half2 h0 = __float22half2_rn(make_float2(v.x, v.y));
        __half2 h1 = __float22half2_rn(make_float2(v.z, v.w));
        uint2 o;
        o.x = *(uint32_t*)&h0;
        o.y = *(uint32_t*)&h1;
        out[i] = o;
    }
}
__global__ __launch_bounds__(256) void f2h4_k(
    const float4* i0, uint2* o0, int n0,
    const float4* i1, uint2* o1, int n1,
    const float4* i2, uint2* o2, int n2,
    const float4* i3, uint2* o3, int n3)
{
    int gid = blockIdx.x * 256 + threadIdx.x;
    int gstride = gridDim.x * 256;
    f2h_range(i0, o0, n0, gid, gstride);
    f2h_range(i1, o1, n1, gid, gstride);
    f2h_range(i2, o2, n2, gid, gstride);
    f2h_range(i3, o3, n3, gid, gstride);
}

// ================= R11 GEMM mainloop (256 threads, warp grid 2x4, tile 64x32) ======
#define GEMM_MAINLOOP(A_, Bm_, K_)                                                   \
    const int NK = (K_) / BK;                                                        \
    const int row8 = tid >> 3, seg = tid & 7;                                        \
    const int lane = tid & 31, w = tid >> 5;                                         \
    const int wm = (w >> 2) * 64;                                                    \
    const int wn = (w & 3) * 32;                                                     \
    const int tr = lane >> 2, tc = lane & 3;                                         \
    const uint32_t mrowA = (uint32_t)(wm + (lane & 15));                             \
    const uint32_t swzA  = (mrowA & 7) << 4;                                         \
    const uint32_t la16  = (uint32_t)(lane & 16);                                    \
    const uint32_t aRow  = mrowA * 128;                                              \
    const uint32_t nrowB = (uint32_t)(wn + (lane & 7) + ((lane & 16) >> 1));         \
    const uint32_t swzB  = (nrowB & 7) << 4;                                         \
    const uint32_t lb16  = (uint32_t)((lane & 8) << 1);                              \
    const uint32_t bRow  = nrowB * 128;                                              \
    float acc[4][4][4];                                                              \
    _Pragma("unroll")                                                                \
    for (int i = 0; i < 4; i++)                                                      \
        _Pragma("unroll")                                                            \
        for (int j = 0; j < 4; j++)                                                  \
            _Pragma("unroll")                                                        \
            for (int q = 0; q < 4; q++) acc[i][j][q] = 0.f;                          \
    auto load_stage = [&](int s, int kidx) {                                         \
        uint32_t a_s = sbase + 1024 + s * STAGE_BYTES;                               \
        uint32_t b_s = a_s + BM * BK * 2;                                            \
        const __half* ag = (A_) + (size_t)bm * (K_) + kidx * BK + seg * 8;           \
        const __half* bg = (Bm_) + (size_t)bn * (K_) + kidx * BK + seg * 8;          \
        _Pragma("unroll")                                                            \
        for (int i = 0; i < 4; i++) {                                                \
            int r = row8 + i * 32;                                                   \
            uint32_t off = r * 128 + seg * 16;                                       \
            uint32_t sw = off ^ ((off >> 3) & 0x70);                                 \
            cp_async16(a_s + sw, ag + (size_t)r * (K_));                             \
            cp_async16(b_s + sw, bg + (size_t)r * (K_));                             \
        }                                                                            \
        asm volatile("cp.async.commit_group;" ::: "memory");                         \
    };                                                                               \
    load_stage(0, 0); load_stage(1, 1);                                              \
    int buf = 0, lbuf = 2;                                                           \
    for (int ks = 0; ks < NK; ks++) {                                                \
        if (ks + 1 < NK) asm volatile("cp.async.wait_group 1;" ::: "memory");        \
        else             asm volatile("cp.async.wait_group 0;" ::: "memory");        \
        __syncthreads();                                                             \
        if (ks + 2 < NK) {                                                           \
            load_stage(lbuf, ks + 2);                                                \
            lbuf = (lbuf == STAGES - 1) ? 0 : lbuf + 1;                              \
        }                                                                            \
        const uint32_t a_s = sbase + 1024 + buf * STAGE_BYTES;                       \
        const uint32_t b_s = a_s + BM * BK * 2;                                      \
        buf = (buf == STAGES - 1) ? 0 : buf + 1;                                     \
        _Pragma("unroll")                                                            \
        for (int ksl = 0; ksl < 4; ksl++) {                                          \
            const uint32_t cbA = (((uint32_t)(ksl * 32)) | la16) ^ swzA;             \
            const uint32_t cbB = (((uint32_t)(ksl * 32)) | lb16) ^ swzB;             \
            uint32_t av[4][4], bq[2][4];                                             \
            _Pragma("unroll")                                                        \
            for (int i = 0; i < 4; i++)                                              \
                ldsm_x4(av[i], a_s + aRow + i * 2048 + cbA);                         \
            _Pragma("unroll")                                                        \
            for (int p = 0; p < 2; p++)                                              \
                ldsm_x4(bq[p], b_s + bRow + p * 2048 + cbB);                         \
            _Pragma("unroll")                                                        \
            for (int i = 0; i < 4; i++) {                                            \
                _Pragma("unroll")                                                    \
                for (int j = 0; j < 4; j++)                                          \
                    mma16n8k16h(acc[i][j], av[i], (j & 1) ? bq[j >> 1] + 2 : bq[j >> 1]); \
            }                                                                        \
        }                                                                            \
    }

// ---------------- merged projection GEMM: [silu(x Wqkv^T) | sigmoid(x Wg^T)] ----------------
__global__ __launch_bounds__(256, 2) void gemm_proj(
    const __half* __restrict__ A, const __half* __restrict__ Bm)
{
    extern __shared__ char smem[];
    const uint32_t sbase = smem_u32(smem);
    const int tid = threadIdx.x;
    const int bm = blockIdx.y * BM, bn = blockIdx.x * BN;

    GEMM_MAINLOOP(A, Bm, D_)

    if (bn < QKVS_) {
        __half* C = g_qkvh;
#pragma unroll
        for (int i = 0; i < 4; i++) {
#pragma unroll
            for (int j = 0; j < 4; j++) {
                int r0 = bm + wm + i * 16 + tr;
                int c0 = bn + wn + j * 8 + 2 * tc;
                __half2 v0 = __float22half2_rn(make_float2(act_apply(acc[i][j][0], 1),
                                                           act_apply(acc[i][j][1], 1)));
                __half2 v1 = __float22half2_rn(make_float2(act_apply(acc[i][j][2], 1),
                                                           act_apply(acc[i][j][3], 1)));
                *(__half2*)(C + (size_t)r0 * QKVS_ + c0) = v0;
                *(__half2*)(C + (size_t)(r0 + 8) * QKVS_ + c0) = v1;
            }
        }
    } else {
        __half* C = g_gateh;
        int cbase = bn - QKVS_;
#pragma unroll
        for (int i = 0; i < 4; i++) {
#pragma unroll
            for (int j = 0; j < 4; j++) {
                int r0 = bm + wm + i * 16 + tr;
                int c0 = cbase + wn + j * 8 + 2 * tc;
                __half2 v0 = __float22half2_rn(make_float2(act_apply(acc[i][j][0], 2),
                                                           act_apply(acc[i][j][1], 2)));
                __half2 v1 = __float22half2_rn(make_float2(act_apply(acc[i][j][2], 2),
                                                           act_apply(acc[i][j][3], 2)));
                *(__half2*)(C + (size_t)r0 * D_ + c0) = v0;
                *(__half2*)(C + (size_t)(r0 + 8) * D_ + c0) = v1;
            }
        }
    }
}

// ---------------- final projection GEMM: out = y @ Wo^T (fp32 out) ----------------
__global__ __launch_bounds__(256, 2) void gemm_out(
    const __half* __restrict__ A, const __half* __restrict__ Bm,
    float* __restrict__ C)
{
    extern __shared__ char smem[];
    const uint32_t sbase = smem_u32(smem);
    const int tid = threadIdx.x;
    const int bm = blockIdx.y * BM, bn = blockIdx.x * BN;

    GEMM_MAINLOOP(A, Bm, D_)

#pragma unroll
    for (int i = 0; i < 4; i++) {
#pragma unroll
        for (int j = 0; j < 4; j++) {
            int r0 = bm + wm + i * 16 + tr;
            int c0 = bn + wn + j * 8 + 2 * tc;
            float2 v0, v1;
            v0.x = acc[i][j][0];
            v0.y = acc[i][j][1];
            v1.x = acc[i][j][2];
            v1.y = acc[i][j][3];
            *(float2*)(C + (size_t)r0 * D_ + c0) = v0;
            *(float2*)(C + (size_t)(r0 + 8) * D_ + c0) = v1;
        }
    }
}

// ---------------- phase 1: fp16 tensor-core intra attention + KV summary ----------------
#define ROWB 256
#define P1_SMEM (3*128*ROWB + 3*128*4)
__global__ __launch_bounds__(256, 2) void attn_phase1(const float* __restrict__ slope)
{
    extern __shared__ char smc[];
    const uint32_t sb = smem_u32(smc);
    const uint32_t bQ = sb;                    // Q -> S
    const uint32_t bK = sb + 128*ROWB;         // K natural
    const uint32_t bV = sb + 2*128*ROWB;       // V natural
    float* ei = (float*)(smc + 3*128*ROWB);
    float* ej = ei + 128;
    __half* wdh = (__half*)(ej + 128);

    const int c = blockIdx.x, h = blockIdx.y, b = blockIdx.z;
    const int tid = threadIdx.x, lane = tid & 31, w = tid >> 5;
    const int tr = lane >> 2, tc = lane & 3;
    const int wm = (w >> 2) * 64, wn = (w & 3) * 32;
    const float sl = slope[h];
    if (tid < 128) {
        ei[tid] = __expf(-sl * (float)tid);
        ej[tid] = __expf( sl * (float)tid);
        wdh[tid] = __float2half(__expf(-sl * (float)(127 - tid)));
    }

    const __half* base = g_qkvh + ((size_t)(b*N_ + c*CH_)) * QKVS_ + h * (3*HD_);

#pragma unroll
    for (int it = 0; it < 8; it++) {
        int idx = tid + it * 256;
        int row = idx >> 4, sg = idx & 15;
        uint32_t cb = (uint32_t)(sg * 16) ^ (uint32_t)((row & 7) << 4);
        const __half* rp = base + (size_t)row * QKVS_;
        *(uint4*)(smc + (bQ - sb) + row*ROWB + cb) = *(const uint4*)(rp + sg*8);
        *(uint4*)(smc + (bK - sb) + row*ROWB + cb) = *(const uint4*)(rp + HD_ + sg*8);
        *(uint4*)(smc + (bV - sb) + row*ROWB + cb) = *(const uint4*)(rp + 2*HD_ + sg*8);
    }
    __syncthreads();

    const uint32_t swz  = (uint32_t)((lane & 7) << 4);
    const uint32_t la16 = (uint32_t)(lane & 16);
    const uint32_t lb16 = (uint32_t)((lane & 8) << 1);
    const uint32_t aOff = (uint32_t)((wm + (lane & 15)) * ROWB);
    const uint32_t bOff = (uint32_t)((wn + (lane & 7) + ((lane & 16) >> 1)) * ROWB);
    const uint32_t aTrow = (uint32_t)(((lane & 7) + ((lane & 16) >> 1)) * ROWB);
    const uint32_t bTrow = (uint32_t)(((lane & 7) + (lane & 8)) * ROWB);
    uint32_t aTcol[4];
#pragma unroll
    for (int i = 0; i < 4; i++)
        aTcol[i] = (uint32_t)((wm + i*16 + (lane & 8)) * 2) ^ swz;
    uint32_t bTcol[2];
#pragma unroll
    for (int p = 0; p < 2; p++)
        bTcol[p] = (uint32_t)((wn + p*16 + ((lane & 16) >> 1)) * 2) ^ swz;

    float acc[4][4][4];
    // ---- mma1: S = Q K^T ----
#pragma unroll
    for (int i = 0; i < 4; i++)
#pragma unroll
        for (int j = 0; j < 4; j++)
#pragma unroll
            for (int q = 0; q < 4; q++) acc[i][j][q] = 0.f;
#pragma unroll
    for (int kc = 0; kc < 8; kc++) {
        uint32_t cbA = (((uint32_t)(kc * 32)) | la16) ^ swz;
        uint32_t cbB = (((uint32_t)(kc * 32)) | lb16) ^ swz;
        uint32_t av[4][4], bq[2][4];
#pragma unroll
        for (int i = 0; i < 4; i++) ldsm_x4(av[i], bQ + aOff + i*4096 + cbA);
#pragma unroll
        for (int p = 0; p < 2; p++) ldsm_x4(bq[p], bK + bOff + p*4096 + cbB);
#pragma unroll
        for (int i = 0; i < 4; i++)
#pragma unroll
            for (int j = 0; j < 4; j++)
                mma16n8k16h(acc[i][j], av[i], (j & 1) ? bq[j >> 1] + 2 : bq[j >> 1]);
    }
    __syncthreads();

    // ---- decay mask, store S (fp16) into bQ ----
#pragma unroll
    for (int i = 0; i < 4; i++) {
        int i0 = wm + i*16 + tr;
        float ei0 = ei[i0], ei1 = ei[i0 + 8];
        uint32_t sz = (uint32_t)((i0 & 7) << 4);
#pragma unroll
        for (int j = 0; j < 4; j++) {
            int j0 = wn + j*8 + 2*tc;
            float ej0 = ej[j0], ej1 = ej[j0 + 1];
            float s00 = (j0     <= i0    ) ? acc[i][j][0] * (ei0*ej0) : 0.f;
            float s01 = (j0 + 1 <= i0    ) ? acc[i][j][1] * (ei0*ej1) : 0.f;
            float s10 = (j0     <= i0 + 8) ? acc[i][j][2] * (ei1*ej0) : 0.f;
            float s11 = (j0 + 1 <= i0 + 8) ? acc[i][j][3] * (ei1*ej1) : 0.f;
            uint32_t dc = ((uint32_t)(j0 * 2)) ^ sz;
            *(__half2*)(smc + (bQ - sb) + i0*ROWB + dc) =
                __float22half2_rn(make_float2(s00, s01));
            *(__half2*)(smc + (bQ - sb) + (i0+8)*ROWB + dc) =
                __float22half2_rn(make_float2(s10, s11));
        }
    }
    __syncthreads();

    // ---- mma2 (O = S V) + mma3 (A = V^T (K*w)) fused loop ----
    float acco[4][4][4];
#pragma unroll
    for (int i = 0; i < 4; i++)
#pragma unroll
        for (int j = 0; j < 4; j++)
#pragma unroll
            for (int q = 0; q < 4; q++) { acc[i][j][q] = 0.f; acco[i][j][q] = 0.f; }

    const int kt = 2 * (lane & 3);

#pragma unroll
    for (int kc = 0; kc < 8; kc++) {
        uint32_t cbA = (((uint32_t)(kc * 32)) | la16) ^ swz;
        uint32_t kRow = (uint32_t)(kc * 16) * ROWB;
        uint32_t av[4][4], bq[2][4];
#pragma unroll
        for (int i = 0; i < 4; i++) ldsm_x4(av[i], bQ + aOff + i*4096 + cbA);
#pragma unroll
        for (int p = 0; p < 2; p++) ldsm_x4_t(bq[p], bV + bTrow + kRow + bTcol[p]);
#pragma unroll
        for (int i = 0; i < 4; i++)
#pragma unroll
            for (int j = 0; j < 4; j++)
                mma16n8k16h(acco[i][j], av[i], (j & 1) ? bq[j >> 1] + 2 : bq[j >> 1]);
        uint32_t wlo = *(const uint32_t*)(wdh + kc*16 + kt);
        uint32_t whi = *(const uint32_t*)(wdh + kc*16 + kt + 8);
        uint32_t avv[4][4], bk[2][4];
#pragma unroll
        for (int i = 0; i < 4; i++) ldsm_x4_t(avv[i], bV + aTrow + kRow + aTcol[i]);
#pragma unroll
        for (int p = 0; p < 2; p++) {
            ldsm_x4_t(bk[p], bK + bTrow + kRow + bTcol[p]);
            __half2 w0 = *(__half2*)&wlo, w1 = *(__half2*)&whi;
            __half2* bh = (__half2*)bk[p];
            bh[0] = __hmul2(bh[0], w0);
            bh[1] = __hmul2(bh[1], w1);
            bh[2] = __hmul2(bh[2], w0);
            bh[3] = __hmul2(bh[3], w1);
        }
#pragma unroll
        for (int i = 0; i < 4; i++)
#pragma unroll
            for (int j = 0; j < 4; j++)
                mma16n8k16h(acc[i][j], avv[i], (j & 1) ? bk[j >> 1] + 2 : bk[j >> 1]);
    }
    {
        float* obase = g_O + ((size_t)(b*N_ + c*CH_)) * D_ + h*HD_;
        float* abase = g_A + (((size_t)(b*H_ + h))*NC_ + c) * (HD_*HD_);
#pragma unroll
        for (int i = 0; i < 4; i++) {
            int i0 = wm + i*16 + tr;
#pragma unroll
            for (int j = 0; j < 4; j++) {
                int j0 = wn + j*8 + 2*tc;
                float2 v0 = { acco[i][j][0], acco[i][j][1] };
                float2 v1 = { acco[i][j][2], acco[i][j][3] };
                *(float2*)(obase + (size_t)i0 * D_ + j0) = v0;
                *(float2*)(obase + (size_t)(i0+8) * D_ + j0) = v1;
                float2 a0 = { acc[i][j][0], acc[i][j][1] };
                float2 a1 = { acc[i][j][2], acc[i][j][3] };
                *(float2*)(abase + i0*HD_ + j0) = a0;
                *(float2*)(abase + (i0+8)*HD_ + j0) = a1;
            }
        }
    }
}

// ---------------- phase 2: chunk-state scan, vectorized (4 consecutive elems/thread) ----------------
__global__ __launch_bounds__(256) void attn_phase2(
    const float* __restrict__ past_kv, const float* __restrict__ slope,
    float* __restrict__ kv_out, int write_kv)
{
    const int bh = blockIdx.x;
    const int h = bh & (H_ - 1);
    const int tid = threadIdx.x;
    const float lamC = __expf(-slope[h] * (float)CH_);
    const size_t i0 = (size_t)blockIdx.y * 1024 + tid * 4;   // 16*256*4 = 16384
    const size_t pb = (size_t)bh * (HD_*HD_);
    float st[4];
#pragma unroll
    for (int t = 0; t < 4; t++) {
        size_t i = i0 + t;
        st[t] = past_kv[pb + (i & 127)*HD_ + (i >> 7)];   // transposed gather (once)
    }
    float4 cur = *(const float4*)(g_A + ((size_t)bh*NC_) * (HD_*HD_) + i0);
    for (int c = 0; c < NC_; c++) {
        const size_t kb = ((size_t)bh*NC_ + c) * (HD_*HD_);
        float4 nxt;
        if (c + 1 < NC_)
            nxt = *(const float4*)(g_A + kb + (HD_*HD_) + i0);
        // vectorized fp16 store of current state
        __half2 h0 = __float22half2_rn(make_float2(st[0], st[1]));
        __half2 h1 = __float22half2_rn(make_float2(st[2], st[3]));
        uint2 pk;
        pk.x = *(uint32_t*)&h0;
        pk.y = *(uint32_t*)&h1;
        *(uint2*)(g_KVh + kb + i0) = pk;
        st[0] = fmaf(lamC, st[0], cur.x);
        st[1] = fmaf(lamC, st[1], cur.y);
        st[2] = fmaf(lamC, st[2], cur.z);
        st[3] = fmaf(lamC, st[3], cur.w);
        cur = nxt;
    }
    if (write_kv) {
#pragma unroll
        for (int t = 0; t < 4; t++) {
            size_t i = i0 + t;
            kv_out[pb + (i & 127)*HD_ + (i >> 7)] = st[t];
        }
    }
}

// ---------------- phase 3: O += lambda^(i+1) * Q KV0 (fp16 tensor cores) ----------------
#define P3_SMEM (2*128*ROWB + 128*4)
__global__ __launch_bounds__(256, 2) void attn_phase3(const float* __restrict__ slope)
{
    extern __shared__ char smc[];
    const uint32_t sb = smem_u32(smc);
    const uint32_t bQ  = sb;
    const uint32_t bKV = sb + 128*ROWB;
    float* e2 = (float*)(smc + 2*128*ROWB);

    const int c = blockIdx.x, h = blockIdx.y, b = blockIdx.z;
    const int tid = threadIdx.x, lane = tid & 31, w = tid >> 5;
    const int tr = lane >> 2, tc = lane & 3;
    const int wm = (w >> 2) * 64, wn = (w & 3) * 32;
    const float sl = slope[h];
    if (tid < 128) e2[tid] = __expf(-sl * (float)(tid + 1));

    const __half* qbase  = g_qkvh + ((size_t)(b*N_ + c*CH_)) * QKVS_ + h * (3*HD_);
    const __half* kvbase = g_KVh + (((size_t)(b*H_ + h))*NC_ + c) * (HD_*HD_);
#pragma unroll
    for (int it = 0; it < 8; it++) {
        int idx = tid + it * 256;
        int row = idx >> 4, sg = idx & 15;
        uint32_t cb = (uint32_t)(sg * 16) ^ (uint32_t)((row & 7) << 4);
        *(uint4*)(smc + (bQ - sb) + row*ROWB + cb) =
            *(const uint4*)(qbase + (size_t)row * QKVS_ + sg*8);
        *(uint4*)(smc + (bKV - sb) + row*ROWB + cb) =
            *(const uint4*)(kvbase + (size_t)row * HD_ + sg*8);
    }
    __syncthreads();

    const uint32_t swz   = (uint32_t)((lane & 7) << 4);
    const uint32_t la16  = (uint32_t)(lane & 16);
    const uint32_t lb16  = (uint32_t)((lane & 8) << 1);
    const uint32_t aOff  = (uint32_t)((wm + (lane & 15)) * ROWB);
    const uint32_t bOff  = (uint32_t)((wn + (lane & 7) + ((lane & 16) >> 1)) * ROWB);

    float acc[4][4][4];
#pragma unroll
    for (int i = 0; i < 4; i++)
#pragma unroll
        for (int j = 0; j < 4; j++)
#pragma unroll
            for (int q = 0; q < 4; q++) acc[i][j][q] = 0.f;

#pragma unroll
    for (int kc = 0; kc < 8; kc++) {
        uint32_t cbA = (((uint32_t)(kc * 32)) | la16) ^ swz;
        uint32_t cbB = (((uint32_t)(kc * 32)) | lb16) ^ swz;
        uint32_t av[4][4], bq[2][4];
#pragma unroll
        for (int i = 0; i < 4; i++) ldsm_x4(av[i], bQ + aOff + i*4096 + cbA);
#pragma unroll
        for (int p = 0; p < 2; p++) ldsm_x4(bq[p], bKV + bOff + p*4096 + cbB);
#pragma unroll
        for (int i = 0; i < 4; i++)
#pragma unroll
            for (int j = 0; j < 4; j++)
                mma16n8k16h(acc[i][j], av[i], (j & 1) ? bq[j >> 1] + 2 : bq[j >> 1]);
    }

    float* obase = g_O + ((size_t)(b*N_ + c*CH_)) * D_ + h*HD_;
#pragma unroll
    for (int i = 0; i < 4; i++) {
        int i0 = wm + i*16 + tr;
        float s0 = e2[i0], s1 = e2[i0 + 8];
#pragma unroll
        for (int j = 0; j < 4; j++) {
            int j0 = wn + j*8 + 2*tc;
            float2* p0 = (float2*)(obase + (size_t)i0 * D_ + j0);
            float2* p1 = (float2*)(obase + (size_t)(i0+8) * D_ + j0);
            float2 v0 = *p0, v1 = *p1;
            v0.x = fmaf(s0, acc[i][j][0], v0.x);
            v0.y = fmaf(s0, acc[i][j][1], v0.y);
            v1.x = fmaf(s1, acc[i][j][2], v1.x);
            v1.y = fmaf(s1, acc[i][j][3], v1.y);
            *p0 = v0; *p1 = v1;
        }
    }
}

// ---------------- RMSNorm * gate(fp16) -> y (fp16) ----------------
__global__ __launch_bounds__(256) void rmsnorm_gate_k(const float* __restrict__ norm_w)
{
    const int row = blockIdx.x;
    const int tid = threadIdx.x;
    const float4* o4 = (const float4*)(g_O + (size_t)row * D_);
    const __half2* gh = (const __half2*)(g_gateh + (size_t)row * D_);
    const float4* w4 = (const float4*)norm_w;
    __half2* yh = (__half2*)(g_yh + (size_t)row * D_);

    float4 v0 = o4[tid], v1 = o4[tid + 256];
    float s = v0.x*v0.x + v0.y*v0.y + v0.z*v0.z + v0.w*v0.w
            + v1.x*v1.x + v1.y*v1.y + v1.z*v1.z + v1.w*v1.w;
#pragma unroll
    for (int off = 16; off; off >>= 1) s += __shfl_xor_sync(0xffffffffu, s, off);
    __shared__ float red[8];
    if ((tid & 31) == 0) red[tid >> 5] = s;
    __syncthreads();
    float tot = red[0] + red[1] + red[2] + red[3] + red[4] + red[5] + red[6] + red[7];
    float r = rsqrtf(tot * (1.f / (float)D_) + 1e-6f);

    float2 g0 = __half22float2(gh[2*tid]);
    float2 g1 = __half22float2(gh[2*tid + 1]);
    float2 g2 = __half22float2(gh[2*(tid + 256)]);
    float2 g3 = __half22float2(gh[2*(tid + 256) + 1]);
    float4 w0 = w4[tid], w1 = w4[tid + 256];
    yh[2*tid]         = __float22half2_rn(make_float2(g0.x*w0.x*v0.x*r, g0.y*w0.y*v0.y*r));
    yh[2*tid+1]       = __float22half2_rn(make_float2(g1.x*w0.z*v0.z*r, g1.y*w0.w*v0.w*r));
    yh[2*(tid+256)]   = __float22half2_rn(make_float2(g2.x*w1.x*v1.x*r, g2.y*w1.y*v1.y*r));
    yh[2*(tid+256)+1] = __float22half2_rn(make_float2(g3.x*w1.z*v1.z*r, g3.y*w1.w*v1.w*r));
}

// ---------------- launch ----------------
extern "C" void kernel_launch(void* const* d_in, const int* in_sizes, int n_in,
                              void* d_out, int out_size)
{
    const float* x       = (const float*)d_in[0];
    const float* past_kv = (const float*)d_in[1];
    const float* slope   = (const float*)d_in[2];
    const float* w_qkv   = (const float*)d_in[3];
    const float* w_gate  = (const float*)d_in[4];
    const float* w_out   = (const float*)d_in[5];
    const float* norm_w  = (const float*)d_in[6];
    float* out = (float*)d_out;

    __half *xh_p, *yh_p, *wch_p, *woh_p;
    cudaGetSymbolAddress((void**)&xh_p, g_xh);
    cudaGetSymbolAddress((void**)&yh_p, g_yh);
    cudaGetSymbolAddress((void**)&wch_p, g_wch);
    cudaGetSymbolAddress((void**)&woh_p, g_woh);

    cudaFuncSetAttribute(attn_phase1, cudaFuncAttributeMaxDynamicSharedMemorySize, P1_SMEM);
    cudaFuncSetAttribute(attn_phase3, cudaFuncAttributeMaxDynamicSharedMemorySize, P3_SMEM);
    cudaFuncSetAttribute(gemm_proj, cudaFuncAttributeMaxDynamicSharedMemorySize, SM_TC_TOTAL);
    cudaFuncSetAttribute(gemm_out, cudaFuncAttributeMaxDynamicSharedMemorySize, SM_TC_TOTAL);

    const int M = B_ * N_;   // 4096

    f2h4_k<<<2048, 256>>>((const float4*)x, (uint2*)xh_p, (B_*N_*D_)/4,
                          (const float4*)w_qkv, (uint2*)wch_p, (QKVS_*D_)/4,
                          (const float4*)w_gate, (uint2*)(wch_p + (size_t)QKVS_*D_), (H_*HD_*D_)/4,
                          (const float4*)w_out, (uint2*)woh_p, (D_*H_*HD_)/4);

    gemm_proj<<<dim3(NCOMB/BN, M/BM), 256, SM_TC_TOTAL>>>(xh_p, wch_p);
    attn_phase1<<<dim3(NC_, H_, B_), 256, P1_SMEM>>>(slope);
    int write_kv = (out_size >= (int)(B_*N_*D_ + B_*H_*HD_*HD_)) ? 1 : 0;
    attn_phase2<<<dim3(B_*H_, 16), 256>>>(past_kv, slope, out + (size_t)B_*N_*D_, write_kv);
    attn_phase3<<<dim3(NC_, H_, B_), 256, P3_SMEM>>>(slope);
    rmsnorm_gate_k<<<M, 256>>>(norm_w);
    gemm_out<<<dim3(D_/BN, M/BM), 256, SM_TC_TOTAL>>>(yh_p, woh_p, out);
}